// round 12
// baseline (speedup 1.0000x reference)
#include <cuda_runtime.h>
#include <math.h>

// Problem constants
#define BB   4
#define TT   4096
#define DD   1024
#define HH   4
#define DKK  256
#define NTOK (BB * TT)          // 16384 tokens
#define NROW (NTOK * HH)        // 65536 head-rows of 256
#define NG   (TT / 4)           // 1024 4-step groups per (b,h)

// ---------------------------------------------------------------------------
// Scratch (device globals)
// ---------------------------------------------------------------------------
__device__ float g_q[NTOK * DD];
__device__ float g_k[NTOK * DD];
__device__ float g_v[NTOK * DD];
__device__ float g_g[NTOK * DD];
__device__ float g_o[NTOK * DD];
__device__ float g_beta[NTOK * HH];
__device__ float g_dec[NTOK * HH];
__device__ float g_wt[5][DD * DD];            // transposed weights [N][K]
__device__ float g_gram[BB * HH * NG * 16];   // per-group Gram scalars

// ---------------------------------------------------------------------------
// Small PTX helpers
// ---------------------------------------------------------------------------
__device__ __forceinline__ unsigned f2tf32(float f) {
    unsigned u; asm("cvt.rna.tf32.f32 %0, %1;" : "=r"(u) : "f"(f)); return u;
}
__device__ __forceinline__ void ldsm4(unsigned* r, unsigned addr) {
    asm volatile("ldmatrix.sync.aligned.m8n8.x4.shared.b16 {%0,%1,%2,%3}, [%4];"
                 : "=r"(r[0]), "=r"(r[1]), "=r"(r[2]), "=r"(r[3]) : "r"(addr));
}
__device__ __forceinline__ void mma8(float* c, const unsigned* a, const unsigned* b) {
    asm volatile("mma.sync.aligned.m16n8k8.row.col.f32.tf32.tf32.f32 "
                 "{%0,%1,%2,%3},{%4,%5,%6,%7},{%8,%9},{%0,%1,%2,%3};"
                 : "+f"(c[0]), "+f"(c[1]), "+f"(c[2]), "+f"(c[3])
                 : "r"(a[0]), "r"(a[1]), "r"(a[2]), "r"(a[3]),
                   "r"(b[0]), "r"(b[1]));
}
typedef unsigned long long u64;
__device__ __forceinline__ u64 pk2(float lo, float hi) {
    u64 r; asm("mov.b64 %0, {%1,%2};" : "=l"(r) : "f"(lo), "f"(hi)); return r;
}
__device__ __forceinline__ float psum2(u64 v) {
    float a, b; asm("mov.b64 {%0,%1}, %2;" : "=f"(a), "=f"(b) : "l"(v)); return a + b;
}
__device__ __forceinline__ u64 fma2(u64 a, u64 b, u64 c) {
    u64 d; asm("fma.rn.f32x2 %0, %1, %2, %3;" : "=l"(d) : "l"(a), "l"(b), "l"(c)); return d;
}
__device__ __forceinline__ u64 mul2(u64 a, u64 b) {
    u64 d; asm("mul.rn.f32x2 %0, %1, %2;" : "=l"(d) : "l"(a), "l"(b)); return d;
}
__device__ __forceinline__ float sigmoid_f(float z) { return 1.f / (1.f + expf(-z)); }
__device__ __forceinline__ float softplus_f(float z) {
    return fmaxf(z, 0.f) + log1pf(expf(-fabsf(z)));
}

// ---------------------------------------------------------------------------
// 1024x1024 transpose: out[n][k] = in[k][n]
// ---------------------------------------------------------------------------
__global__ void __launch_bounds__(256)
transpose_kernel(const float* __restrict__ in, float* __restrict__ out)
{
    __shared__ float tl[32][33];
    const int tx = threadIdx.x, ty = threadIdx.y;
    const int x  = blockIdx.x * 32 + tx;
    const int y0 = blockIdx.y * 32;
#pragma unroll
    for (int j = 0; j < 32; j += 8)
        tl[ty + j][tx] = in[(size_t)(y0 + ty + j) * DD + x];
    __syncthreads();
    const int ox  = blockIdx.y * 32 + tx;
    const int oy0 = blockIdx.x * 32;
#pragma unroll
    for (int j = 0; j < 32; j += 8)
        out[(size_t)(oy0 + ty + j) * DD + ox] = tl[tx][ty + j];
}

// ---------------------------------------------------------------------------
// tf32 tensor-core GEMM: C = A[M,K] @ Bt[rows,K]^T  (fp32 in/out)
// 128x128x32 CTA tile, 8 warps (4Mx2N), m16n8k8, XOR-swizzled smem,
// double-buffered (one __syncthreads per K-tile). blockIdx.x spans up to
// 4 concatenated output matrices (8 col-tiles each).
// ---------------------------------------------------------------------------
#define TBM 128
#define TBN 128
#define TBK 32

__global__ void __launch_bounds__(256)
gemm_tf32_kernel(const float* __restrict__ A, const float* __restrict__ Bt,
                 float* __restrict__ C0, float* __restrict__ C1,
                 float* __restrict__ C2, float* __restrict__ C3)
{
    extern __shared__ unsigned dsm[];
    unsigned* As = dsm;           // [2][128*32]
    unsigned* Bs = dsm + 8192;    // [2][128*32]

    const int K = DD, N = DD;
    const int tid   = threadIdx.x;
    const int warp  = tid >> 5;
    const int lane  = tid & 31;
    const int warpM = warp & 3;
    const int warpN = warp >> 2;
    const int blockRow = blockIdx.y * TBM;
    const int bColG    = blockIdx.x * TBN;          // row in Bt space
    const int matid    = blockIdx.x >> 3;
    const int blockCol = (blockIdx.x & 7) * TBN;    // col within output matrix
    float* C = (matid == 0) ? C0 : (matid == 1) ? C1 : (matid == 2) ? C2 : C3;

    const int srow = tid >> 3;           // 0..31
    const int schk = tid & 7;            // 0..7

    const unsigned asBase = (unsigned)__cvta_generic_to_shared(As);
    const unsigned bsBase = (unsigned)__cvta_generic_to_shared(Bs);

    const int rowA  = warpM * 32 + (lane & 15);
    const int cbitA = (lane >> 4) & 1;
    const int maskA = rowA & 7;
    unsigned rbA[2];
#pragma unroll
    for (int mt = 0; mt < 2; mt++)
        rbA[mt] = asBase + ((unsigned)(rowA + mt * 16) << 7);

    const int rowB  = warpN * 64 + (lane & 7) + (((lane >> 4) & 1) << 3);
    const int cbitB = (lane >> 3) & 1;
    const int maskB = rowB & 7;
    unsigned rbB[4];
#pragma unroll
    for (int p = 0; p < 4; p++)
        rbB[p] = bsBase + ((unsigned)(rowB + p * 16) << 7);

    float acc[2][8][4];
#pragma unroll
    for (int mt = 0; mt < 2; mt++)
#pragma unroll
        for (int nt = 0; nt < 8; nt++)
#pragma unroll
            for (int i = 0; i < 4; i++) acc[mt][nt][i] = 0.f;

    const float* Ag = A  + (size_t)(blockRow + srow) * K + schk * 4;
    const float* Bg = Bt + (size_t)(bColG   + srow) * K + schk * 4;

    float4 ra[4], rb[4];
#pragma unroll
    for (int i = 0; i < 4; i++) {
        ra[i] = *(const float4*)(Ag + (size_t)(32 * i) * K);
        rb[i] = *(const float4*)(Bg + (size_t)(32 * i) * K);
    }
#pragma unroll
    for (int i = 0; i < 4; i++) {
        const int row = srow + 32 * i;
        const int idx = row * 32 + ((schk ^ (row & 7)) << 2);
        *(uint4*)&As[idx] = make_uint4(f2tf32(ra[i].x), f2tf32(ra[i].y),
                                       f2tf32(ra[i].z), f2tf32(ra[i].w));
        *(uint4*)&Bs[idx] = make_uint4(f2tf32(rb[i].x), f2tf32(rb[i].y),
                                       f2tf32(rb[i].z), f2tf32(rb[i].w));
    }
    __syncthreads();

    const int nt_iters = K / TBK;
    for (int t = 0; t < nt_iters; t++) {
        const int cur = t & 1;
        const unsigned bo = (unsigned)cur * 16384u;     // byte offset into buffer
        const int nxtOff  = (cur ^ 1) * 4096;           // element offset

        if (t + 1 < nt_iters) {
            Ag += TBK; Bg += TBK;
#pragma unroll
            for (int i = 0; i < 4; i++) {
                ra[i] = *(const float4*)(Ag + (size_t)(32 * i) * K);
                rb[i] = *(const float4*)(Bg + (size_t)(32 * i) * K);
            }
        }

#pragma unroll
        for (int kk = 0; kk < 4; kk++) {
            unsigned af[2][4];
#pragma unroll
            for (int mt = 0; mt < 2; mt++) {
                const unsigned addr = rbA[mt] + bo +
                    ((unsigned)(((2 * kk + cbitA) ^ maskA)) << 4);
                ldsm4(af[mt], addr);
            }
            unsigned bf[4][4];
#pragma unroll
            for (int p = 0; p < 4; p++) {
                const unsigned addr = rbB[p] + bo +
                    ((unsigned)(((2 * kk + cbitB) ^ maskB)) << 4);
                ldsm4(bf[p], addr);
            }
#pragma unroll
            for (int mt = 0; mt < 2; mt++)
#pragma unroll
                for (int p = 0; p < 4; p++) {
                    mma8(acc[mt][2 * p],     af[mt], &bf[p][0]);
                    mma8(acc[mt][2 * p + 1], af[mt], &bf[p][2]);
                }
        }

        if (t + 1 < nt_iters) {
#pragma unroll
            for (int i = 0; i < 4; i++) {
                const int row = srow + 32 * i;
                const int idx = nxtOff + row * 32 + ((schk ^ (row & 7)) << 2);
                *(uint4*)&As[idx] = make_uint4(f2tf32(ra[i].x), f2tf32(ra[i].y),
                                               f2tf32(ra[i].z), f2tf32(ra[i].w));
                *(uint4*)&Bs[idx] = make_uint4(f2tf32(rb[i].x), f2tf32(rb[i].y),
                                               f2tf32(rb[i].z), f2tf32(rb[i].w));
            }
        }
        __syncthreads();
    }

#pragma unroll
    for (int mt = 0; mt < 2; mt++) {
        const int row = blockRow + warpM * 32 + mt * 16 + (lane >> 2);
#pragma unroll
        for (int nt = 0; nt < 8; nt++) {
            const int col = blockCol + warpN * 64 + nt * 8 + (lane & 3) * 2;
            *(float2*)&C[(size_t)row * N + col] =
                make_float2(acc[mt][nt][0], acc[mt][nt][1]);
            *(float2*)&C[(size_t)(row + 8) * N + col] =
                make_float2(acc[mt][nt][2], acc[mt][nt][3]);
        }
    }
}

// ---------------------------------------------------------------------------
// beta / dec projections: one warp per token
// ---------------------------------------------------------------------------
__global__ void __launch_bounds__(256)
betadec_kernel(const float* __restrict__ x, const float* __restrict__ Wb,
               const float* __restrict__ Wa, const float* __restrict__ A_log,
               const float* __restrict__ dt_bias,
               float* __restrict__ Beta, float* __restrict__ Dec)
{
    const int warp = (blockIdx.x * blockDim.x + threadIdx.x) >> 5;
    const int lane = threadIdx.x & 31;
    if (warp >= NTOK) return;

    const float* xr = x + (size_t)warp * DD;
    const float4* Wb4 = (const float4*)Wb;
    const float4* Wa4 = (const float4*)Wa;

    float b0 = 0.f, b1 = 0.f, b2 = 0.f, b3 = 0.f;
    float a0 = 0.f, a1 = 0.f, a2 = 0.f, a3 = 0.f;
#pragma unroll 4
    for (int i = 0; i < DD / 32; i++) {
        const int d = i * 32 + lane;
        const float xv = xr[d];
        const float4 wb = Wb4[d];
        const float4 wa = Wa4[d];
        b0 = fmaf(xv, wb.x, b0); b1 = fmaf(xv, wb.y, b1);
        b2 = fmaf(xv, wb.z, b2); b3 = fmaf(xv, wb.w, b3);
        a0 = fmaf(xv, wa.x, a0); a1 = fmaf(xv, wa.y, a1);
        a2 = fmaf(xv, wa.z, a2); a3 = fmaf(xv, wa.w, a3);
    }
#pragma unroll
    for (int off = 16; off; off >>= 1) {
        b0 += __shfl_xor_sync(0xffffffffu, b0, off);
        b1 += __shfl_xor_sync(0xffffffffu, b1, off);
        b2 += __shfl_xor_sync(0xffffffffu, b2, off);
        b3 += __shfl_xor_sync(0xffffffffu, b3, off);
        a0 += __shfl_xor_sync(0xffffffffu, a0, off);
        a1 += __shfl_xor_sync(0xffffffffu, a1, off);
        a2 += __shfl_xor_sync(0xffffffffu, a2, off);
        a3 += __shfl_xor_sync(0xffffffffu, a3, off);
    }
    if (lane == 0) {
        float bl[4] = {b0, b1, b2, b3};
        float al[4] = {a0, a1, a2, a3};
#pragma unroll
        for (int h = 0; h < HH; h++) {
            Beta[warp * HH + h] = sigmoid_f(bl[h]);
            Dec[warp * HH + h]  = expf(-expf(A_log[h]) * softplus_f(al[h] + dt_bias[h]));
        }
    }
}

// ---------------------------------------------------------------------------
// q/k L2 normalization
// ---------------------------------------------------------------------------
__global__ void __launch_bounds__(256)
qknorm_kernel(float* __restrict__ Q, float* __restrict__ Kk)
{
    const int warp = (blockIdx.x * blockDim.x + threadIdx.x) >> 5;
    const int lane = threadIdx.x & 31;
    if (warp >= NROW) return;

    float* qr = Q + (size_t)warp * DKK;
    float* kr = Kk + (size_t)warp * DKK;

    float4 q0 = *(float4*)(qr + lane * 8);
    float4 q1 = *(float4*)(qr + lane * 8 + 4);
    float4 k0 = *(float4*)(kr + lane * 8);
    float4 k1 = *(float4*)(kr + lane * 8 + 4);

    float sq = q0.x*q0.x + q0.y*q0.y + q0.z*q0.z + q0.w*q0.w
             + q1.x*q1.x + q1.y*q1.y + q1.z*q1.z + q1.w*q1.w;
    float sk = k0.x*k0.x + k0.y*k0.y + k0.z*k0.z + k0.w*k0.w
             + k1.x*k1.x + k1.y*k1.y + k1.z*k1.z + k1.w*k1.w;
#pragma unroll
    for (int off = 16; off; off >>= 1) {
        sq += __shfl_xor_sync(0xffffffffu, sq, off);
        sk += __shfl_xor_sync(0xffffffffu, sk, off);
    }
    const float qs = rsqrtf(sq + 1e-6f) * 0.0625f;
    const float ks = rsqrtf(sk + 1e-6f);

    q0.x *= qs; q0.y *= qs; q0.z *= qs; q0.w *= qs;
    q1.x *= qs; q1.y *= qs; q1.z *= qs; q1.w *= qs;
    k0.x *= ks; k0.y *= ks; k0.z *= ks; k0.w *= ks;
    k1.x *= ks; k1.y *= ks; k1.z *= ks; k1.w *= ks;

    *(float4*)(qr + lane * 8)     = q0;
    *(float4*)(qr + lane * 8 + 4) = q1;
    *(float4*)(kr + lane * 8)     = k0;
    *(float4*)(kr + lane * 8 + 4) = k1;
}

// ---------------------------------------------------------------------------
// Gram precompute: per (b,h,group of 4 steps), 16 dot products of length 256:
//  [K10,K20,K21,K30,K31,K32, Q00,Q10,Q11,Q20,Q21,Q22,Q30,Q31,Q32,Q33]
//  where Kij = k_i.k_j, Qij = q_i.k_j (normalized q/k). One warp per group.
// ---------------------------------------------------------------------------
__global__ void __launch_bounds__(256)
gram_kernel(const float* __restrict__ Q, const float* __restrict__ Kmat,
            float* __restrict__ Gram)
{
    const int gw   = (blockIdx.x * blockDim.x + threadIdx.x) >> 5;
    const int lane = threadIdx.x & 31;
    if (gw >= BB * HH * NG) return;
    const int g  = gw % NG;
    const int bh = gw / NG;
    const int h  = bh % HH;
    const int b  = bh / HH;

    const size_t base = ((size_t)b * TT) * DD + (size_t)h * DKK
                      + (size_t)(g * 4) * DD + lane * 8;

    float kf[4][8], qf[4][8];
#pragma unroll
    for (int i = 0; i < 4; i++) {
        float4 x0 = *(const float4*)(Kmat + base + (size_t)i * DD);
        float4 x1 = *(const float4*)(Kmat + base + (size_t)i * DD + 4);
        kf[i][0]=x0.x; kf[i][1]=x0.y; kf[i][2]=x0.z; kf[i][3]=x0.w;
        kf[i][4]=x1.x; kf[i][5]=x1.y; kf[i][6]=x1.z; kf[i][7]=x1.w;
        float4 y0 = *(const float4*)(Q + base + (size_t)i * DD);
        float4 y1 = *(const float4*)(Q + base + (size_t)i * DD + 4);
        qf[i][0]=y0.x; qf[i][1]=y0.y; qf[i][2]=y0.z; qf[i][3]=y0.w;
        qf[i][4]=y1.x; qf[i][5]=y1.y; qf[i][6]=y1.z; qf[i][7]=y1.w;
    }

    float d[16];
#pragma unroll
    for (int i = 0; i < 16; i++) d[i] = 0.f;
#pragma unroll
    for (int e = 0; e < 8; e++) {
        d[0]  = fmaf(kf[1][e], kf[0][e], d[0]);   // K10
        d[1]  = fmaf(kf[2][e], kf[0][e], d[1]);   // K20
        d[2]  = fmaf(kf[2][e], kf[1][e], d[2]);   // K21
        d[3]  = fmaf(kf[3][e], kf[0][e], d[3]);   // K30
        d[4]  = fmaf(kf[3][e], kf[1][e], d[4]);   // K31
        d[5]  = fmaf(kf[3][e], kf[2][e], d[5]);   // K32
        d[6]  = fmaf(qf[0][e], kf[0][e], d[6]);   // Q00
        d[7]  = fmaf(qf[1][e], kf[0][e], d[7]);   // Q10
        d[8]  = fmaf(qf[1][e], kf[1][e], d[8]);   // Q11
        d[9]  = fmaf(qf[2][e], kf[0][e], d[9]);   // Q20
        d[10] = fmaf(qf[2][e], kf[1][e], d[10]);  // Q21
        d[11] = fmaf(qf[2][e], kf[2][e], d[11]);  // Q22
        d[12] = fmaf(qf[3][e], kf[0][e], d[12]);  // Q30
        d[13] = fmaf(qf[3][e], kf[1][e], d[13]);  // Q31
        d[14] = fmaf(qf[3][e], kf[2][e], d[14]);  // Q32
        d[15] = fmaf(qf[3][e], kf[3][e], d[15]);  // Q33
    }
#pragma unroll
    for (int i = 0; i < 16; i++)
#pragma unroll
        for (int off = 16; off; off >>= 1)
            d[i] += __shfl_xor_sync(0xffffffffu, d[i], off);

    if (lane == 0) {
        float* out = Gram + (size_t)gw * 16;
        *(float4*)(out + 0)  = make_float4(d[0],  d[1],  d[2],  d[3]);
        *(float4*)(out + 4)  = make_float4(d[4],  d[5],  d[6],  d[7]);
        *(float4*)(out + 8)  = make_float4(d[8],  d[9],  d[10], d[11]);
        *(float4*)(out + 12) = make_float4(d[12], d[13], d[14], d[15]);
    }
}

// ---------------------------------------------------------------------------
// Gated delta-rule recurrence — 4-step groups, Gram-assisted.
// Grid (8, H, B): CTA owns (b, h) and 32 DV columns. 8 warps cover DK=256
// (32 rows each); lane = column. State slice in 16 packed f32x2 registers.
// Per group: 8 dots vs group-entry state -> 1 barrier -> scalar recursion
// with precomputed Grams -> rank-4 state update -> 1 barrier.
// Reduction buffer layout [pair][warp][lane] keeps lane innermost:
// all STS/LDS in the cross-warp reduce are bank-conflict-free.
// ---------------------------------------------------------------------------
__global__ void __launch_bounds__(256)
recur4_kernel(const float* __restrict__ Q, const float* __restrict__ Kmat,
              const float* __restrict__ V, const float* __restrict__ Beta,
              const float* __restrict__ Dec, const float* __restrict__ Gram,
              float* __restrict__ O)
{
    const int gcol = blockIdx.x;
    const int h    = blockIdx.y;
    const int b    = blockIdx.z;
    const int tid  = threadIdx.x;
    const int w    = tid >> 5;
    const int lane = tid & 31;

    __shared__ __align__(16) float sv[2][8][256];    // [buf][vec: k0..k3,q0..q3][row]
    __shared__ __align__(16) float2 part[4][8][32];  // [dot-pair][warp][lane]

    u64 S2[16];
#pragma unroll
    for (int i = 0; i < 16; i++) S2[i] = 0ull;

    const size_t base = ((size_t)b * TT) * DD + (size_t)h * DKK;
    // staging source: warp w stages vector w (k0..k3 for w<4, q0..q3 for w>=4)
    const float* stp = ((w < 4) ? Kmat : Q) + base + (size_t)(w & 3) * DD + lane * 8;
    const float* vp  = V + base + gcol * 32 + lane;
    float*       op  = O + base + gcol * 32 + lane;
    const float* bp  = Beta + ((size_t)b * TT) * HH + h;
    const float* dp  = Dec  + ((size_t)b * TT) * HH + h;
    const float* gp  = Gram + ((size_t)(b * HH + h) * NG) * 16;

    // prologue: stage group 0
    {
        float4 s0 = *(const float4*)(stp);
        float4 s1 = *(const float4*)(stp + 4);
        *(float4*)&sv[0][w][lane * 8]     = s0;
        *(float4*)&sv[0][w][lane * 8 + 4] = s1;
    }
    __syncthreads();

#pragma unroll 1
    for (int g = 0; g < NG; g++) {
        const int cur = g & 1;
        const int nxt = cur ^ 1;
        const int t0  = g * 4;

        // prefetch next group's staging data
        float4 s0, s1;
        if (g + 1 < NG) {
            const float* p = stp + (size_t)(g + 1) * 4 * DD;
            s0 = *(const float4*)p;
            s1 = *(const float4*)(p + 4);
        }
        // uniform per-group scalars (L1-broadcast)
        const float4 gr0 = *(const float4*)(gp + (size_t)g * 16);
        const float4 gr1 = *(const float4*)(gp + (size_t)g * 16 + 4);
        const float4 gr2 = *(const float4*)(gp + (size_t)g * 16 + 8);
        const float4 gr3 = *(const float4*)(gp + (size_t)g * 16 + 12);
        float be[4], de[4], vvv[4];
#pragma unroll
        for (int i = 0; i < 4; i++) {
            be[i]  = bp[(size_t)(t0 + i) * HH];
            de[i]  = dp[(size_t)(t0 + i) * HH];
            vvv[i] = vp[(size_t)(t0 + i) * DD];
        }

        // 8 dots vs current state (this warp's 32-row slice)
        float dot[8];
#pragma unroll
        for (int vi = 0; vi < 8; vi++) {
            const ulonglong2* vec = (const ulonglong2*)&sv[cur][vi][w * 32];
            u64 acc = 0ull;
#pragma unroll
            for (int c = 0; c < 8; c++) {
                ulonglong2 x = vec[c];
                acc = fma2(x.x, S2[2 * c],     acc);
                acc = fma2(x.y, S2[2 * c + 1], acc);
            }
            dot[vi] = psum2(acc);
        }
#pragma unroll
        for (int p = 0; p < 4; p++)
            part[p][w][lane] = make_float2(dot[2 * p], dot[2 * p + 1]);
        __syncthreads();                                     // bar 1

        // cross-warp reduce (conflict-free: lane innermost)
        float a0 = 0.f, a1 = 0.f, a2 = 0.f, a3 = 0.f;
        float r0 = 0.f, r1 = 0.f, r2 = 0.f, r3 = 0.f;
#pragma unroll
        for (int ww = 0; ww < 8; ww++) {
            float2 p0 = part[0][ww][lane];
            float2 p1 = part[1][ww][lane];
            float2 p2 = part[2][ww][lane];
            float2 p3 = part[3][ww][lane];
            a0 += p0.x; a1 += p0.y; a2 += p1.x; a3 += p1.y;
            r0 += p2.x; r1 += p2.y; r2 += p3.x; r3 += p3.y;
        }

        const float K10 = gr0.x, K20 = gr0.y, K21 = gr0.z, K30 = gr0.w;
        const float K31 = gr1.x, K32 = gr1.y, Q00 = gr1.z, Q10 = gr1.w;
        const float Q11 = gr2.x, Q20 = gr2.y, Q21 = gr2.z, Q22 = gr2.w;
        const float Q30 = gr3.x, Q31 = gr3.y, Q32 = gr3.z, Q33 = gr3.w;
        const float d0 = de[0], d1 = de[1], d2 = de[2], d3 = de[3];
        const float d01 = d0 * d1, d012 = d01 * d2, D3 = d012 * d3;
        const float d12 = d1 * d2, d123 = d12 * d3, d23 = d2 * d3;

        const float u0 = be[0] * (vvv[0] - d0 * a0);
        const float u1 = be[1] * (vvv[1] - d1 * (d0 * a1 + K10 * u0));
        const float u2 = be[2] * (vvv[2] - d2 * (d01 * a2 + d1 * K20 * u0 + K21 * u1));
        const float u3 = be[3] * (vvv[3] - d3 * (d012 * a3 + d12 * K30 * u0
                                                 + d2 * K31 * u1 + K32 * u2));

        const float o0 = d0   * r0 + Q00 * u0;
        const float o1 = d01  * r1 + d1 * Q10 * u0 + Q11 * u1;
        const float o2 = d012 * r2 + d12 * Q20 * u0 + d2 * Q21 * u1 + Q22 * u2;
        const float o3 = D3   * r3 + d123 * Q30 * u0 + d23 * Q31 * u1
                       + d3 * Q32 * u2 + Q33 * u3;

        const float c0 = d123 * u0, c1 = d23 * u1, c2 = d3 * u2, c3 = u3;
        const u64 D3p = pk2(D3, D3);
        const u64 c0p = pk2(c0, c0), c1p = pk2(c1, c1);
        const u64 c2p = pk2(c2, c2), c3p = pk2(c3, c3);

        // rank-4 state update: S = D3*S + c0*k0 + c1*k1 + c2*k2 + c3*k3
        const ulonglong2* k0v = (const ulonglong2*)&sv[cur][0][w * 32];
        const ulonglong2* k1v = (const ulonglong2*)&sv[cur][1][w * 32];
        const ulonglong2* k2v = (const ulonglong2*)&sv[cur][2][w * 32];
        const ulonglong2* k3v = (const ulonglong2*)&sv[cur][3][w * 32];
#pragma unroll
        for (int c = 0; c < 8; c++) {
            ulonglong2 x0 = k0v[c], x1 = k1v[c], x2 = k2v[c], x3 = k3v[c];
            u64 acc = mul2(c0p, x0.x);
            acc = fma2(c1p, x1.x, acc);
            acc = fma2(c2p, x2.x, acc);
            acc = fma2(c3p, x3.x, acc);
            S2[2 * c] = fma2(D3p, S2[2 * c], acc);
            u64 accb = mul2(c0p, x0.y);
            accb = fma2(c1p, x1.y, accb);
            accb = fma2(c2p, x2.y, accb);
            accb = fma2(c3p, x3.y, accb);
            S2[2 * c + 1] = fma2(D3p, S2[2 * c + 1], accb);
        }

        // stage next group into the other buffer
        if (g + 1 < NG) {
            *(float4*)&sv[nxt][w][lane * 8]     = s0;
            *(float4*)&sv[nxt][w][lane * 8 + 4] = s1;
        }
        // outputs (computed redundantly; warp 0 stores)
        if (w == 0) {
            op[(size_t)(t0 + 0) * DD] = o0;
            op[(size_t)(t0 + 1) * DD] = o1;
            op[(size_t)(t0 + 2) * DD] = o2;
            op[(size_t)(t0 + 3) * DD] = o3;
        }
        __syncthreads();                                     // bar 2
    }
}

// ---------------------------------------------------------------------------
// Epilogue: gated RMSNorm per head-row, in place.
// ---------------------------------------------------------------------------
__global__ void __launch_bounds__(256)
epilogue_kernel(float* __restrict__ Oarr, const float* __restrict__ G,
                const float* __restrict__ norm_w)
{
    const int warp = (blockIdx.x * blockDim.x + threadIdx.x) >> 5;
    const int lane = threadIdx.x & 31;
    if (warp >= NROW) return;

    float* orow = Oarr + (size_t)warp * DKK;
    const float* grow = G + (size_t)warp * DKK;

    float4 o0 = *(float4*)(orow + lane * 8);
    float4 o1 = *(float4*)(orow + lane * 8 + 4);

    float s = o0.x*o0.x + o0.y*o0.y + o0.z*o0.z + o0.w*o0.w
            + o1.x*o1.x + o1.y*o1.y + o1.z*o1.z + o1.w*o1.w;
#pragma unroll
    for (int off = 16; off; off >>= 1)
        s += __shfl_xor_sync(0xffffffffu, s, off);
    const float scale = rsqrtf(s * (1.f / 256.f) + 1e-5f);

    float4 g0 = *(const float4*)(grow + lane * 8);
    float4 g1 = *(const float4*)(grow + lane * 8 + 4);
    float4 w0 = *(const float4*)(norm_w + lane * 8);
    float4 w1 = *(const float4*)(norm_w + lane * 8 + 4);

    o0.x = o0.x * scale * w0.x * (g0.x * sigmoid_f(g0.x));
    o0.y = o0.y * scale * w0.y * (g0.y * sigmoid_f(g0.y));
    o0.z = o0.z * scale * w0.z * (g0.z * sigmoid_f(g0.z));
    o0.w = o0.w * scale * w0.w * (g0.w * sigmoid_f(g0.w));
    o1.x = o1.x * scale * w1.x * (g1.x * sigmoid_f(g1.x));
    o1.y = o1.y * scale * w1.y * (g1.y * sigmoid_f(g1.y));
    o1.z = o1.z * scale * w1.z * (g1.z * sigmoid_f(g1.z));
    o1.w = o1.w * scale * w1.w * (g1.w * sigmoid_f(g1.w));

    *(float4*)(orow + lane * 8)     = o0;
    *(float4*)(orow + lane * 8 + 4) = o1;
}

// ---------------------------------------------------------------------------
// Host launcher
// ---------------------------------------------------------------------------
extern "C" void kernel_launch(void* const* d_in, const int* in_sizes, int n_in,
                              void* d_out, int out_size)
{
    const float* x       = (const float*)d_in[0];
    const float* Wq      = (const float*)d_in[1];
    const float* Wk      = (const float*)d_in[2];
    const float* Wv      = (const float*)d_in[3];
    const float* Wb      = (const float*)d_in[4];
    const float* Wa      = (const float*)d_in[5];
    const float* A_log   = (const float*)d_in[6];
    const float* dt_bias = (const float*)d_in[7];
    const float* Wg      = (const float*)d_in[8];
    const float* norm_w  = (const float*)d_in[9];
    const float* Wo      = (const float*)d_in[10];
    float* out = (float*)d_out;

    float *q, *k, *v, *g, *o, *bet, *dec, *wt, *gram;
    cudaGetSymbolAddress((void**)&q,    g_q);
    cudaGetSymbolAddress((void**)&k,    g_k);
    cudaGetSymbolAddress((void**)&v,    g_v);
    cudaGetSymbolAddress((void**)&g,    g_g);
    cudaGetSymbolAddress((void**)&o,    g_o);
    cudaGetSymbolAddress((void**)&bet,  g_beta);
    cudaGetSymbolAddress((void**)&dec,  g_dec);
    cudaGetSymbolAddress((void**)&wt,   g_wt);
    cudaGetSymbolAddress((void**)&gram, g_gram);

    float* wtq = wt + 0 * (size_t)DD * DD;
    float* wtk = wt + 1 * (size_t)DD * DD;
    float* wtv = wt + 2 * (size_t)DD * DD;
    float* wtg = wt + 3 * (size_t)DD * DD;
    float* wto = wt + 4 * (size_t)DD * DD;

    static int smem_set = 0;
    if (!smem_set) {
        cudaFuncSetAttribute(gemm_tf32_kernel,
                             cudaFuncAttributeMaxDynamicSharedMemorySize, 65536);
        smem_set = 1;
    }

    dim3 tgrid(32, 32), tblk(32, 8);
    transpose_kernel<<<tgrid, tblk>>>(Wq, wtq);
    transpose_kernel<<<tgrid, tblk>>>(Wk, wtk);
    transpose_kernel<<<tgrid, tblk>>>(Wv, wtv);
    transpose_kernel<<<tgrid, tblk>>>(Wg, wtg);
    transpose_kernel<<<tgrid, tblk>>>(Wo, wto);

    // fused q/k/v/g projections: Bt = [Wq^T; Wk^T; Wv^T; Wg^T] (4096 rows)
    dim3 fusedGrid(32, NTOK / TBM);
    gemm_tf32_kernel<<<fusedGrid, 256, 65536>>>(x, wtq, q, k, v, g);

    betadec_kernel<<<NTOK / 8, 256>>>(x, Wb, Wa, A_log, dt_bias, bet, dec);
    qknorm_kernel<<<NROW / 8, 256>>>(q, k);

    gram_kernel<<<(BB * HH * NG) / 8, 256>>>(q, k, gram);
    recur4_kernel<<<dim3(8, HH, BB), 256>>>(q, k, v, bet, dec, gram, o);

    epilogue_kernel<<<NROW / 8, 256>>>(o, g, norm_w);

    dim3 outGrid(8, NTOK / TBM);
    gemm_tf32_kernel<<<outGrid, 256, 65536>>>(o, wto, out, out, out, out);
}

// round 13
// speedup vs baseline: 1.1865x; 1.1865x over previous
#include <cuda_runtime.h>
#include <math.h>

// Problem constants
#define BB   4
#define TT   4096
#define DD   1024
#define HH   4
#define DKK  256
#define NTOK (BB * TT)          // 16384 tokens
#define NROW (NTOK * HH)        // 65536 head-rows of 256

// ---------------------------------------------------------------------------
// Scratch (device globals)
// ---------------------------------------------------------------------------
__device__ float g_q[NTOK * DD];
__device__ float g_k[NTOK * DD];
__device__ float g_v[NTOK * DD];
__device__ float g_g[NTOK * DD];
__device__ float g_o[NTOK * DD];
__device__ float g_beta[NTOK * HH];
__device__ float g_dec[NTOK * HH];
__device__ float g_wt[5][DD * DD];   // transposed weights [N][K]

// ---------------------------------------------------------------------------
// Small PTX helpers
// ---------------------------------------------------------------------------
__device__ __forceinline__ unsigned f2tf32(float f) {
    unsigned u; asm("cvt.rna.tf32.f32 %0, %1;" : "=r"(u) : "f"(f)); return u;
}
__device__ __forceinline__ void ldsm4(unsigned* r, unsigned addr) {
    asm volatile("ldmatrix.sync.aligned.m8n8.x4.shared.b16 {%0,%1,%2,%3}, [%4];"
                 : "=r"(r[0]), "=r"(r[1]), "=r"(r[2]), "=r"(r[3]) : "r"(addr));
}
__device__ __forceinline__ void mma8(float* c, const unsigned* a, const unsigned* b) {
    asm volatile("mma.sync.aligned.m16n8k8.row.col.f32.tf32.tf32.f32 "
                 "{%0,%1,%2,%3},{%4,%5,%6,%7},{%8,%9},{%0,%1,%2,%3};"
                 : "+f"(c[0]), "+f"(c[1]), "+f"(c[2]), "+f"(c[3])
                 : "r"(a[0]), "r"(a[1]), "r"(a[2]), "r"(a[3]),
                   "r"(b[0]), "r"(b[1]));
}
typedef unsigned long long u64;
__device__ __forceinline__ u64 pk2(float lo, float hi) {
    u64 r; asm("mov.b64 %0, {%1,%2};" : "=l"(r) : "f"(lo), "f"(hi)); return r;
}
__device__ __forceinline__ float psum2(u64 v) {
    float a, b; asm("mov.b64 {%0,%1}, %2;" : "=f"(a), "=f"(b) : "l"(v)); return a + b;
}
__device__ __forceinline__ u64 fma2(u64 a, u64 b, u64 c) {
    u64 d; asm("fma.rn.f32x2 %0, %1, %2, %3;" : "=l"(d) : "l"(a), "l"(b), "l"(c)); return d;
}
__device__ __forceinline__ u64 mul2(u64 a, u64 b) {
    u64 d; asm("mul.rn.f32x2 %0, %1, %2;" : "=l"(d) : "l"(a), "l"(b)); return d;
}
__device__ __forceinline__ float sigmoid_f(float z) { return 1.f / (1.f + expf(-z)); }
__device__ __forceinline__ float softplus_f(float z) {
    return fmaxf(z, 0.f) + log1pf(expf(-fabsf(z)));
}

// ---------------------------------------------------------------------------
// 1024x1024 transpose: out[n][k] = in[k][n]
// ---------------------------------------------------------------------------
__global__ void __launch_bounds__(256)
transpose_kernel(const float* __restrict__ in, float* __restrict__ out)
{
    __shared__ float tl[32][33];
    const int tx = threadIdx.x, ty = threadIdx.y;
    const int x  = blockIdx.x * 32 + tx;
    const int y0 = blockIdx.y * 32;
#pragma unroll
    for (int j = 0; j < 32; j += 8)
        tl[ty + j][tx] = in[(size_t)(y0 + ty + j) * DD + x];
    __syncthreads();
    const int ox  = blockIdx.y * 32 + tx;
    const int oy0 = blockIdx.x * 32;
#pragma unroll
    for (int j = 0; j < 32; j += 8)
        out[(size_t)(oy0 + ty + j) * DD + ox] = tl[tx][ty + j];
}

// ---------------------------------------------------------------------------
// tf32 tensor-core GEMM: C[M,N] = A[M,K] @ Bt[N,K]^T  (fp32 in/out)
// 128x128x32 CTA tile, 8 warps (4Mx2N), m16n8k8, XOR-swizzled static smem.
// (Exact R5 kernel — measured-good.)
// ---------------------------------------------------------------------------
#define TBM 128
#define TBN 128
#define TBK 32

__global__ void __launch_bounds__(256)
gemm_tf32_kernel(const float* __restrict__ A, const float* __restrict__ Bt,
                 float* __restrict__ C, int M, int N, int K)
{
    __shared__ __align__(16) unsigned As[TBM * TBK];
    __shared__ __align__(16) unsigned Bs[TBN * TBK];

    const int tid   = threadIdx.x;
    const int warp  = tid >> 5;
    const int lane  = tid & 31;
    const int warpM = warp & 3;
    const int warpN = warp >> 2;
    const int blockRow = blockIdx.y * TBM;
    const int blockCol = blockIdx.x * TBN;

    const int srow = tid >> 3;           // 0..31
    const int schk = tid & 7;            // 0..7

    const unsigned asBase = (unsigned)__cvta_generic_to_shared(As);
    const unsigned bsBase = (unsigned)__cvta_generic_to_shared(Bs);

    const int rowA  = warpM * 32 + (lane & 15);
    const int cbitA = (lane >> 4) & 1;
    const int maskA = rowA & 7;
    unsigned rbA[2];
#pragma unroll
    for (int mt = 0; mt < 2; mt++)
        rbA[mt] = asBase + ((unsigned)(rowA + mt * 16) << 7);

    const int rowB  = warpN * 64 + (lane & 7) + (((lane >> 4) & 1) << 3);
    const int cbitB = (lane >> 3) & 1;
    const int maskB = rowB & 7;
    unsigned rbB[4];
#pragma unroll
    for (int p = 0; p < 4; p++)
        rbB[p] = bsBase + ((unsigned)(rowB + p * 16) << 7);

    float acc[2][8][4];
#pragma unroll
    for (int mt = 0; mt < 2; mt++)
#pragma unroll
        for (int nt = 0; nt < 8; nt++)
#pragma unroll
            for (int i = 0; i < 4; i++) acc[mt][nt][i] = 0.f;

    const float* Ag = A  + (size_t)(blockRow + srow) * K + schk * 4;
    const float* Bg = Bt + (size_t)(blockCol + srow) * K + schk * 4;

    float4 ra[4], rb[4];
#pragma unroll
    for (int i = 0; i < 4; i++) {
        ra[i] = *(const float4*)(Ag + (size_t)(32 * i) * K);
        rb[i] = *(const float4*)(Bg + (size_t)(32 * i) * K);
    }
#pragma unroll
    for (int i = 0; i < 4; i++) {
        const int row = srow + 32 * i;
        const int idx = row * 32 + ((schk ^ (row & 7)) << 2);
        *(uint4*)&As[idx] = make_uint4(f2tf32(ra[i].x), f2tf32(ra[i].y),
                                       f2tf32(ra[i].z), f2tf32(ra[i].w));
        *(uint4*)&Bs[idx] = make_uint4(f2tf32(rb[i].x), f2tf32(rb[i].y),
                                       f2tf32(rb[i].z), f2tf32(rb[i].w));
    }
    __syncthreads();

    const int nt_iters = K / TBK;
    for (int t = 0; t < nt_iters; t++) {
        if (t + 1 < nt_iters) {
            Ag += TBK; Bg += TBK;
#pragma unroll
            for (int i = 0; i < 4; i++) {
                ra[i] = *(const float4*)(Ag + (size_t)(32 * i) * K);
                rb[i] = *(const float4*)(Bg + (size_t)(32 * i) * K);
            }
        }

#pragma unroll
        for (int kk = 0; kk < 4; kk++) {
            unsigned af[2][4];
#pragma unroll
            for (int mt = 0; mt < 2; mt++) {
                const unsigned addr = rbA[mt] +
                    ((unsigned)(((2 * kk + cbitA) ^ maskA)) << 4);
                ldsm4(af[mt], addr);
            }
            unsigned bf[4][4];
#pragma unroll
            for (int p = 0; p < 4; p++) {
                const unsigned addr = rbB[p] +
                    ((unsigned)(((2 * kk + cbitB) ^ maskB)) << 4);
                ldsm4(bf[p], addr);
            }
#pragma unroll
            for (int mt = 0; mt < 2; mt++)
#pragma unroll
                for (int p = 0; p < 4; p++) {
                    mma8(acc[mt][2 * p],     af[mt], &bf[p][0]);
                    mma8(acc[mt][2 * p + 1], af[mt], &bf[p][2]);
                }
        }
        __syncthreads();

        if (t + 1 < nt_iters) {
#pragma unroll
            for (int i = 0; i < 4; i++) {
                const int row = srow + 32 * i;
                const int idx = row * 32 + ((schk ^ (row & 7)) << 2);
                *(uint4*)&As[idx] = make_uint4(f2tf32(ra[i].x), f2tf32(ra[i].y),
                                               f2tf32(ra[i].z), f2tf32(ra[i].w));
                *(uint4*)&Bs[idx] = make_uint4(f2tf32(rb[i].x), f2tf32(rb[i].y),
                                               f2tf32(rb[i].z), f2tf32(rb[i].w));
            }
            __syncthreads();
        }
    }

#pragma unroll
    for (int mt = 0; mt < 2; mt++) {
        const int row = blockRow + warpM * 32 + mt * 16 + (lane >> 2);
#pragma unroll
        for (int nt = 0; nt < 8; nt++) {
            const int col = blockCol + warpN * 64 + nt * 8 + (lane & 3) * 2;
            *(float2*)&C[(size_t)row * N + col] =
                make_float2(acc[mt][nt][0], acc[mt][nt][1]);
            *(float2*)&C[(size_t)(row + 8) * N + col] =
                make_float2(acc[mt][nt][2], acc[mt][nt][3]);
        }
    }
}

// ---------------------------------------------------------------------------
// beta / dec projections: one warp per token
// ---------------------------------------------------------------------------
__global__ void __launch_bounds__(256)
betadec_kernel(const float* __restrict__ x, const float* __restrict__ Wb,
               const float* __restrict__ Wa, const float* __restrict__ A_log,
               const float* __restrict__ dt_bias,
               float* __restrict__ Beta, float* __restrict__ Dec)
{
    const int warp = (blockIdx.x * blockDim.x + threadIdx.x) >> 5;
    const int lane = threadIdx.x & 31;
    if (warp >= NTOK) return;

    const float* xr = x + (size_t)warp * DD;
    const float4* Wb4 = (const float4*)Wb;
    const float4* Wa4 = (const float4*)Wa;

    float b0 = 0.f, b1 = 0.f, b2 = 0.f, b3 = 0.f;
    float a0 = 0.f, a1 = 0.f, a2 = 0.f, a3 = 0.f;
#pragma unroll 4
    for (int i = 0; i < DD / 32; i++) {
        const int d = i * 32 + lane;
        const float xv = xr[d];
        const float4 wb = Wb4[d];
        const float4 wa = Wa4[d];
        b0 = fmaf(xv, wb.x, b0); b1 = fmaf(xv, wb.y, b1);
        b2 = fmaf(xv, wb.z, b2); b3 = fmaf(xv, wb.w, b3);
        a0 = fmaf(xv, wa.x, a0); a1 = fmaf(xv, wa.y, a1);
        a2 = fmaf(xv, wa.z, a2); a3 = fmaf(xv, wa.w, a3);
    }
#pragma unroll
    for (int off = 16; off; off >>= 1) {
        b0 += __shfl_xor_sync(0xffffffffu, b0, off);
        b1 += __shfl_xor_sync(0xffffffffu, b1, off);
        b2 += __shfl_xor_sync(0xffffffffu, b2, off);
        b3 += __shfl_xor_sync(0xffffffffu, b3, off);
        a0 += __shfl_xor_sync(0xffffffffu, a0, off);
        a1 += __shfl_xor_sync(0xffffffffu, a1, off);
        a2 += __shfl_xor_sync(0xffffffffu, a2, off);
        a3 += __shfl_xor_sync(0xffffffffu, a3, off);
    }
    if (lane == 0) {
        float bl[4] = {b0, b1, b2, b3};
        float al[4] = {a0, a1, a2, a3};
#pragma unroll
        for (int h = 0; h < HH; h++) {
            Beta[warp * HH + h] = sigmoid_f(bl[h]);
            Dec[warp * HH + h]  = expf(-expf(A_log[h]) * softplus_f(al[h] + dt_bias[h]));
        }
    }
}

// ---------------------------------------------------------------------------
// q/k L2 normalization
// ---------------------------------------------------------------------------
__global__ void __launch_bounds__(256)
qknorm_kernel(float* __restrict__ Q, float* __restrict__ Kk)
{
    const int warp = (blockIdx.x * blockDim.x + threadIdx.x) >> 5;
    const int lane = threadIdx.x & 31;
    if (warp >= NROW) return;

    float* qr = Q + (size_t)warp * DKK;
    float* kr = Kk + (size_t)warp * DKK;

    float4 q0 = *(float4*)(qr + lane * 8);
    float4 q1 = *(float4*)(qr + lane * 8 + 4);
    float4 k0 = *(float4*)(kr + lane * 8);
    float4 k1 = *(float4*)(kr + lane * 8 + 4);

    float sq = q0.x*q0.x + q0.y*q0.y + q0.z*q0.z + q0.w*q0.w
             + q1.x*q1.x + q1.y*q1.y + q1.z*q1.z + q1.w*q1.w;
    float sk = k0.x*k0.x + k0.y*k0.y + k0.z*k0.z + k0.w*k0.w
             + k1.x*k1.x + k1.y*k1.y + k1.z*k1.z + k1.w*k1.w;
#pragma unroll
    for (int off = 16; off; off >>= 1) {
        sq += __shfl_xor_sync(0xffffffffu, sq, off);
        sk += __shfl_xor_sync(0xffffffffu, sk, off);
    }
    const float qs = rsqrtf(sq + 1e-6f) * 0.0625f;
    const float ks = rsqrtf(sk + 1e-6f);

    q0.x *= qs; q0.y *= qs; q0.z *= qs; q0.w *= qs;
    q1.x *= qs; q1.y *= qs; q1.z *= qs; q1.w *= qs;
    k0.x *= ks; k0.y *= ks; k0.z *= ks; k0.w *= ks;
    k1.x *= ks; k1.y *= ks; k1.z *= ks; k1.w *= ks;

    *(float4*)(qr + lane * 8)     = q0;
    *(float4*)(qr + lane * 8 + 4) = q1;
    *(float4*)(kr + lane * 8)     = k0;
    *(float4*)(kr + lane * 8 + 4) = k1;
}

// ---------------------------------------------------------------------------
// Gated delta-rule recurrence — per-step, lazy output reduction.
// Grid (8, H, B): CTA owns (b, h) and 32 DV columns. 8 warps cover DK=256
// (32 rows each); lane = column. State slice in 16 packed f32x2 registers.
// Per step: ONE __syncthreads (pred reduce). Output partials are buffered
// for 8 steps and reduced with one extra barrier per 8 steps (outputs never
// feed back into the recurrence). k/q staging and pred-partial buffers are
// double-buffered; the per-step barrier separates reuse by 2 steps.
// ---------------------------------------------------------------------------
__global__ void __launch_bounds__(256)
recur_kernel(const float* __restrict__ Q, const float* __restrict__ Kmat,
             const float* __restrict__ V, const float* __restrict__ Beta,
             const float* __restrict__ Dec, float* __restrict__ O)
{
    const int g    = blockIdx.x;
    const int h    = blockIdx.y;
    const int b    = blockIdx.z;
    const int tid  = threadIdx.x;
    const int w    = tid >> 5;
    const int lane = tid & 31;

    __shared__ __align__(16) float skq[2][512];      // [buf][ k[256] | q[256] ]
    __shared__ float part1[2][8][32];                // [buf][warp][lane] pred partials
    __shared__ float part2[8][8][32];                // [step&7][warp][lane] out partials

    u64 S2[16];
#pragma unroll
    for (int i = 0; i < 16; i++) S2[i] = 0ull;

    const size_t base = ((size_t)b * TT) * DD + (size_t)h * DKK;
    const float* qp = Q    + base + tid;
    const float* kp = Kmat + base + tid;
    const float* vp = V    + base + g * 32 + lane;
    float*       ob = O    + base + g * 32 + lane;
    const float* bp = Beta + ((size_t)b * TT) * HH + h;
    const float* dp = Dec  + ((size_t)b * TT) * HH + h;

    // prefetch step 0 (v/beta/dec loaded by every thread — broadcast-cached)
    float kn = *kp, qn = *qp, vn = *vp, bn = *bp, dn = *dp;

#pragma unroll 1
    for (int t = 0; t < TT; t++) {
        const int buf = t & 1;
        skq[buf][tid]       = kn;
        skq[buf][256 + tid] = qn;
        const float vt = vn, bt = bn, dt = dn;
        __syncwarp();

        // warp-local slices (written by this warp's own lanes), packed
        u64 k2[16], q2[16];
        {
            const ulonglong2* kk2 = (const ulonglong2*)(&skq[buf][w * 32]);
            const ulonglong2* qq2 = (const ulonglong2*)(&skq[buf][256 + w * 32]);
#pragma unroll
            for (int ii = 0; ii < 8; ii++) {
                ulonglong2 kvv = kk2[ii]; k2[2 * ii] = kvv.x; k2[2 * ii + 1] = kvv.y;
                ulonglong2 qvv = qq2[ii]; q2[2 * ii] = qvv.x; q2[2 * ii + 1] = qvv.y;
            }
        }

        // prefetch t+1
        if (t + 1 < TT) {
            kp += DD; qp += DD; vp += DD; bp += HH; dp += HH;
            kn = *kp; qn = *qp; vn = *vp; bn = *bp; dn = *dp;
        }

        // pred partial on pre-decay state (two chains for ILP)
        u64 ppa = 0ull, ppb = 0ull;
#pragma unroll
        for (int i = 0; i < 8; i++) {
            ppa = fma2(k2[2 * i],     S2[2 * i],     ppa);
            ppb = fma2(k2[2 * i + 1], S2[2 * i + 1], ppb);
        }
        part1[buf][w][lane] = psum2(ppa) + psum2(ppb);
        __syncthreads();                                   // the one per-step barrier

        // cross-warp pred reduce (redundant per thread; conflict-free LDS)
        float pa = 0.f, pb = 0.f;
#pragma unroll
        for (int ww = 0; ww < 8; ww += 2) {
            pa += part1[buf][ww][lane];
            pb += part1[buf][ww + 1][lane];
        }
        const float pred = pa + pb;
        const float u  = bt * (vt - dt * pred);
        const u64 uu   = pk2(u, u);
        const u64 ddp  = pk2(dt, dt);

        // state update + output partial (two chains each)
        u64 ova = 0ull, ovb = 0ull;
#pragma unroll
        for (int i = 0; i < 8; i++) {
            S2[2 * i]     = fma2(ddp, S2[2 * i],     mul2(k2[2 * i],     uu));
            S2[2 * i + 1] = fma2(ddp, S2[2 * i + 1], mul2(k2[2 * i + 1], uu));
            ova = fma2(q2[2 * i],     S2[2 * i],     ova);
            ovb = fma2(q2[2 * i + 1], S2[2 * i + 1], ovb);
        }
        part2[t & 7][w][lane] = psum2(ova) + psum2(ovb);

        // lazy output reduction every 8 steps: warp w reduces step (t-7+w)
        if ((t & 7) == 7) {
            __syncthreads();
            float oa = 0.f, obv = 0.f;
#pragma unroll
            for (int ww = 0; ww < 8; ww += 2) {
                oa  += part2[w][ww][lane];
                obv += part2[w][ww + 1][lane];
            }
            ob[(size_t)(t - 7 + w) * DD] = oa + obv;
        }
    }
}

// ---------------------------------------------------------------------------
// Epilogue: gated RMSNorm per head-row, in place.
// ---------------------------------------------------------------------------
__global__ void __launch_bounds__(256)
epilogue_kernel(float* __restrict__ Oarr, const float* __restrict__ G,
                const float* __restrict__ norm_w)
{
    const int warp = (blockIdx.x * blockDim.x + threadIdx.x) >> 5;
    const int lane = threadIdx.x & 31;
    if (warp >= NROW) return;

    float* orow = Oarr + (size_t)warp * DKK;
    const float* grow = G + (size_t)warp * DKK;

    float4 o0 = *(float4*)(orow + lane * 8);
    float4 o1 = *(float4*)(orow + lane * 8 + 4);

    float s = o0.x*o0.x + o0.y*o0.y + o0.z*o0.z + o0.w*o0.w
            + o1.x*o1.x + o1.y*o1.y + o1.z*o1.z + o1.w*o1.w;
#pragma unroll
    for (int off = 16; off; off >>= 1)
        s += __shfl_xor_sync(0xffffffffu, s, off);
    const float scale = rsqrtf(s * (1.f / 256.f) + 1e-5f);

    float4 g0 = *(const float4*)(grow + lane * 8);
    float4 g1 = *(const float4*)(grow + lane * 8 + 4);
    float4 w0 = *(const float4*)(norm_w + lane * 8);
    float4 w1 = *(const float4*)(norm_w + lane * 8 + 4);

    o0.x = o0.x * scale * w0.x * (g0.x * sigmoid_f(g0.x));
    o0.y = o0.y * scale * w0.y * (g0.y * sigmoid_f(g0.y));
    o0.z = o0.z * scale * w0.z * (g0.z * sigmoid_f(g0.z));
    o0.w = o0.w * scale * w0.w * (g0.w * sigmoid_f(g0.w));
    o1.x = o1.x * scale * w1.x * (g1.x * sigmoid_f(g1.x));
    o1.y = o1.y * scale * w1.y * (g1.y * sigmoid_f(g1.y));
    o1.z = o1.z * scale * w1.z * (g1.z * sigmoid_f(g1.z));
    o1.w = o1.w * scale * w1.w * (g1.w * sigmoid_f(g1.w));

    *(float4*)(orow + lane * 8)     = o0;
    *(float4*)(orow + lane * 8 + 4) = o1;
}

// ---------------------------------------------------------------------------
// Host launcher (graph-capturable: launches only)
// ---------------------------------------------------------------------------
extern "C" void kernel_launch(void* const* d_in, const int* in_sizes, int n_in,
                              void* d_out, int out_size)
{
    const float* x       = (const float*)d_in[0];
    const float* Wq      = (const float*)d_in[1];
    const float* Wk      = (const float*)d_in[2];
    const float* Wv      = (const float*)d_in[3];
    const float* Wb      = (const float*)d_in[4];
    const float* Wa      = (const float*)d_in[5];
    const float* A_log   = (const float*)d_in[6];
    const float* dt_bias = (const float*)d_in[7];
    const float* Wg      = (const float*)d_in[8];
    const float* norm_w  = (const float*)d_in[9];
    const float* Wo      = (const float*)d_in[10];
    float* out = (float*)d_out;

    float *q, *k, *v, *g, *o, *bet, *dec, *wt;
    cudaGetSymbolAddress((void**)&q,   g_q);
    cudaGetSymbolAddress((void**)&k,   g_k);
    cudaGetSymbolAddress((void**)&v,   g_v);
    cudaGetSymbolAddress((void**)&g,   g_g);
    cudaGetSymbolAddress((void**)&o,   g_o);
    cudaGetSymbolAddress((void**)&bet, g_beta);
    cudaGetSymbolAddress((void**)&dec, g_dec);
    cudaGetSymbolAddress((void**)&wt,  g_wt);

    float* wtq = wt + 0 * (size_t)DD * DD;
    float* wtk = wt + 1 * (size_t)DD * DD;
    float* wtv = wt + 2 * (size_t)DD * DD;
    float* wtg = wt + 3 * (size_t)DD * DD;
    float* wto = wt + 4 * (size_t)DD * DD;

    dim3 tgrid(32, 32), tblk(32, 8);
    transpose_kernel<<<tgrid, tblk>>>(Wq, wtq);
    transpose_kernel<<<tgrid, tblk>>>(Wk, wtk);
    transpose_kernel<<<tgrid, tblk>>>(Wv, wtv);
    transpose_kernel<<<tgrid, tblk>>>(Wg, wtg);
    transpose_kernel<<<tgrid, tblk>>>(Wo, wto);

    dim3 gemmGrid(DD / TBN, NTOK / TBM);   // (8, 128)
    gemm_tf32_kernel<<<gemmGrid, 256>>>(x, wtq, q, NTOK, DD, DD);
    gemm_tf32_kernel<<<gemmGrid, 256>>>(x, wtk, k, NTOK, DD, DD);
    gemm_tf32_kernel<<<gemmGrid, 256>>>(x, wtv, v, NTOK, DD, DD);
    gemm_tf32_kernel<<<gemmGrid, 256>>>(x, wtg, g, NTOK, DD, DD);

    betadec_kernel<<<NTOK / 8, 256>>>(x, Wb, Wa, A_log, dt_bias, bet, dec);
    qknorm_kernel<<<NROW / 8, 256>>>(q, k);

    recur_kernel<<<dim3(8, HH, BB), 256>>>(q, k, v, bet, dec, o);

    epilogue_kernel<<<NROW / 8, 256>>>(o, g, norm_w);

    gemm_tf32_kernel<<<gemmGrid, 256>>>(o, wto, out, NTOK, DD, DD);
}